// round 8
// baseline (speedup 1.0000x reference)
#include <cuda_runtime.h>
#include <cuda_fp16.h>
#include <math.h>
#include <stdint.h>

namespace {

constexpr int T_TOK = 8192;
constexpr int DIM   = 512;
constexpr int FDIM  = 2048;
constexpr int NEXP  = 8;
constexpr int MAXB  = 8192;
constexpr int NROWS = 2 * T_TOK;

// CTA 128x128, 8 warps as 2(M) x 4(N), warp tile 64x32, BK=32 (fp16), 4-stage
constexpr int BM = 128, BN = 128, BK = 32;
constexpr int AST = 40;                          // A smem row stride (halves)
constexpr int BST = 136;                         // B smem row stride (halves)
constexpr int A_PLANE = BM * AST * 2;            // 10240 B
constexpr int B_PLANE = BK * BST * 2;            // 8704 B
constexpr int STAGE   = A_PLANE + B_PLANE;       // 18944 B
constexpr int NSTAGE  = 4;
constexpr int SMEM_BYTES = NSTAGE * STAGE;       // 75776 B

// ---- device scratch ----
__device__ int   g_count[NEXP];
__device__ float g_probsum[NEXP];
__device__ int   g_offset[NEXP];
__device__ int   g_tok[NEXP * MAXB];
__device__ int   g_slot[T_TOK * 2];
__device__ float g_slotw[T_TOK * 2];
__device__ __half g_xh[(size_t)T_TOK * DIM];           // fp16 x
__device__ __half g_w1h[(size_t)NEXP * DIM * FDIM];    // fp16 w1 [E][K=D][N=F]
__device__ __half g_w2h[(size_t)NEXP * FDIM * DIM];    // fp16 w2 [E][K=F][N=D]
__device__ __half g_hid[(size_t)NROWS * FDIM];         // fp16 hidden
__device__ float  g_oscr[(size_t)NROWS * DIM];

// ---- PTX helpers ----
__device__ __forceinline__ uint32_t smem_u32(const void* p) {
    uint32_t a;
    asm("{ .reg .u64 t; cvta.to.shared.u64 t, %1; cvt.u32.u64 %0, t; }" : "=r"(a) : "l"(p));
    return a;
}
__device__ __forceinline__ void cp_async16(uint32_t saddr, const void* g) {
    asm volatile("cp.async.cg.shared.global [%0], [%1], 16;" :: "r"(saddr), "l"(g));
}
__device__ __forceinline__ void cp_commit() { asm volatile("cp.async.commit_group;" ::: "memory"); }
__device__ __forceinline__ void cp_wait2()  { asm volatile("cp.async.wait_group 2;" ::: "memory"); }
__device__ __forceinline__ void cp_wait1()  { asm volatile("cp.async.wait_group 1;" ::: "memory"); }
__device__ __forceinline__ void cp_wait0()  { asm volatile("cp.async.wait_group 0;" ::: "memory"); }

__device__ __forceinline__ void ldsm4(uint32_t& r0, uint32_t& r1, uint32_t& r2, uint32_t& r3,
                                      uint32_t a) {
    asm volatile("ldmatrix.sync.aligned.m8n8.x4.shared.b16 {%0,%1,%2,%3}, [%4];"
                 : "=r"(r0), "=r"(r1), "=r"(r2), "=r"(r3) : "r"(a));
}
__device__ __forceinline__ void ldsm4t(uint32_t& r0, uint32_t& r1, uint32_t& r2, uint32_t& r3,
                                       uint32_t a) {
    asm volatile("ldmatrix.sync.aligned.m8n8.x4.trans.shared.b16 {%0,%1,%2,%3}, [%4];"
                 : "=r"(r0), "=r"(r1), "=r"(r2), "=r"(r3) : "r"(a));
}
__device__ __forceinline__ void mma_f16(float c[4], const uint32_t a[4],
                                        uint32_t b0, uint32_t b1) {
    asm volatile(
        "mma.sync.aligned.m16n8k16.row.col.f32.f16.f16.f32 "
        "{%0,%1,%2,%3}, {%4,%5,%6,%7}, {%8,%9}, {%0,%1,%2,%3};"
        : "+f"(c[0]), "+f"(c[1]), "+f"(c[2]), "+f"(c[3])
        : "r"(a[0]), "r"(a[1]), "r"(a[2]), "r"(a[3]), "r"(b0), "r"(b1));
}

// ---- small kernels ----
__global__ void init_k() {
    if (threadIdx.x < NEXP) { g_count[threadIdx.x] = 0; g_probsum[threadIdx.x] = 0.f; }
}

// router + fused x -> fp16 conversion
__global__ void router_k(const float* __restrict__ x, const float* __restrict__ gw) {
    __shared__ float s_gw[DIM * NEXP];
    for (int i = threadIdx.x; i < DIM * NEXP; i += blockDim.x) s_gw[i] = gw[i];
    __syncthreads();

    int t    = (int)((blockIdx.x * blockDim.x + threadIdx.x) >> 5);
    int lane = threadIdx.x & 31;
    if (t >= T_TOK) return;

    const float* xr = x + (size_t)t * DIM;
    __half* xo = g_xh + (size_t)t * DIM;
    float acc[NEXP];
#pragma unroll
    for (int e = 0; e < NEXP; e++) acc[e] = 0.f;
    for (int d = lane; d < DIM; d += 32) {
        float xv = xr[d];
        xo[d] = __float2half_rn(xv);
#pragma unroll
        for (int e = 0; e < NEXP; e++) acc[e] = fmaf(xv, s_gw[d * NEXP + e], acc[e]);
    }
#pragma unroll
    for (int off = 16; off; off >>= 1) {
#pragma unroll
        for (int e = 0; e < NEXP; e++)
            acc[e] += __shfl_xor_sync(0xffffffffu, acc[e], off);
    }
    if (lane != 0) return;

    float mx = acc[0];
#pragma unroll
    for (int e = 1; e < NEXP; e++) mx = fmaxf(mx, acc[e]);
    float p[NEXP]; float s = 0.f;
#pragma unroll
    for (int e = 0; e < NEXP; e++) { p[e] = expf(acc[e] - mx); s += p[e]; }
    float inv = 1.f / s;
#pragma unroll
    for (int e = 0; e < NEXP; e++) { p[e] *= inv; atomicAdd(&g_probsum[e], p[e]); }

    int i0 = 0;
#pragma unroll
    for (int e = 1; e < NEXP; e++) if (p[e] > p[i0]) i0 = e;
    int i1 = (i0 == 0) ? 1 : 0;
#pragma unroll
    for (int e = 0; e < NEXP; e++) if (e != i0 && p[e] > p[i1]) i1 = e;

    float w0 = p[i0], w1 = p[i1];
    float ws = 1.f / (w0 + w1);
    w0 *= ws; w1 *= ws;

    int p0 = atomicAdd(&g_count[i0], 1);
    g_tok[i0 * MAXB + p0] = t;
    g_slot[t * 2 + 0]  = i0 * MAXB + p0;
    g_slotw[t * 2 + 0] = w0;
    int p1 = atomicAdd(&g_count[i1], 1);
    g_tok[i1 * MAXB + p1] = t;
    g_slot[t * 2 + 1]  = i1 * MAXB + p1;
    g_slotw[t * 2 + 1] = w1;
}

// loss + offsets (runs after GEMM launches; combine needs g_offset)
__global__ void finalize_k(float* __restrict__ loss_out) {
    int off = 0;
    for (int e = 0; e < NEXP; e++) { g_offset[e] = off; off += g_count[e]; }
    float s = 0.f;
    for (int e = 0; e < NEXP; e++) {
        float m = g_probsum[e] * (1.f / (float)T_TOK);
        s += m * m;
    }
    *loss_out = (float)NEXP * s;
}

// fp32 -> fp16 elementwise
__global__ void h_conv_k(const float* __restrict__ src, __half* __restrict__ dst, int n4) {
    int i = blockIdx.x * blockDim.x + threadIdx.x;
    if (i >= n4) return;
    float4 v = ((const float4*)src)[i];
    ((__half2*)dst)[2 * i]     = __floats2half2_rn(v.x, v.y);
    ((__half2*)dst)[2 * i + 1] = __floats2half2_rn(v.z, v.w);
}

// ---- fp16 tensor-core FFN GEMM: D[128,128] = A[gather, K] @ B[K, N] ----
template <int KFULL, int NFULL, bool GELU, bool GATHER>
__global__ __launch_bounds__(256, 2) void ffn_k(
    const __half* __restrict__ A, const __half* __restrict__ B,
    const float* __restrict__ bias,
    __half* __restrict__ OutH, float* __restrict__ OutF) {
    const int e  = blockIdx.z;
    const int ne = g_count[e];
    const int m0 = blockIdx.y * BM;
    if (m0 >= ne) return;
    const int n0 = blockIdx.x * BN;
    int base = 0;
#pragma unroll
    for (int i = 0; i < NEXP - 1; i++) base += (i < e) ? g_count[i] : 0;

    extern __shared__ __align__(16) char smem[];
    const uint32_t sb = smem_u32(smem);
    const int tid  = threadIdx.x;
    const int lane = tid & 31;
    const int warp = tid >> 5;
    const int wm   = (warp & 1) * 64;
    const int wn   = (warp >> 1) * 32;

    // ---- cp.async addressing: 2 A-chunks + 2 B-chunks of 16B per thread ----
    const __half* sA[2];
    uint32_t dA[2];
#pragma unroll
    for (int l = 0; l < 2; l++) {
        int idx = tid + l * 256;          // 0..511
        int row = idx >> 2;               // 0..127
        int ch  = idx & 3;
        int r;
        if (GATHER) r = g_tok[e * MAXB + min(m0 + row, ne - 1)];
        else        r = base + min(m0 + row, ne - 1);
        sA[l] = A + (size_t)r * KFULL + ch * 8;
        dA[l] = (uint32_t)(row * (AST * 2) + ch * 16);
    }
    const __half* sB[2];
    uint32_t dB[2];
    const __half* Bp = B + (size_t)e * KFULL * NFULL;
#pragma unroll
    for (int l = 0; l < 2; l++) {
        int idx = tid + l * 256;
        int k  = idx >> 4;
        int ch = idx & 15;
        sB[l] = Bp + (size_t)k * NFULL + n0 + ch * 8;
        dB[l] = (uint32_t)(A_PLANE + k * (BST * 2) + ch * 16);
    }

    auto load_stage = [&](int s, int k0) {
        uint32_t st = sb + (uint32_t)(s * STAGE);
#pragma unroll
        for (int l = 0; l < 2; l++) cp_async16(st + dA[l], sA[l] + k0);
#pragma unroll
        for (int l = 0; l < 2; l++) cp_async16(st + dB[l], sB[l] + (size_t)k0 * NFULL);
    };

    // ---- ldmatrix lane addressing ----
    const int lm = lane >> 3;
    const int aR = (lm & 1) * 8 + (lane & 7);
    const int aK = (lm >> 1) * 8;
    const int bK = (lm & 1) * 8 + (lane & 7);
    const int bN = (lm >> 1) * 8;

    float acc[4][4][4];
#pragma unroll
    for (int i = 0; i < 4; i++)
#pragma unroll
        for (int j = 0; j < 4; j++)
#pragma unroll
            for (int k = 0; k < 4; k++) acc[i][j][k] = 0.f;

    constexpr int KITERS = KFULL / BK;
    load_stage(0, 0);
    cp_commit();
    load_stage(1, BK);
    cp_commit();
    load_stage(2, 2 * BK);
    cp_commit();

    for (int it = 0; it < KITERS; it++) {
        if (it + 1 == KITERS)      cp_wait0();
        else if (it + 2 == KITERS) cp_wait1();
        else                       cp_wait2();
        __syncthreads();
        // issue next prefetch BEFORE compute: overlaps a full iteration of MMA
        if (it + 3 < KITERS) {
            load_stage((it + 3) & 3, (it + 3) * BK);
            cp_commit();
        }
        uint32_t st = sb + (uint32_t)((it & 3) * STAGE);
#pragma unroll
        for (int ks = 0; ks < 2; ks++) {
            const int k0s = ks * 16;
            uint32_t ah[4][4];
#pragma unroll
            for (int mt = 0; mt < 4; mt++) {
                uint32_t a0 = st + (uint32_t)(((wm + mt * 16 + aR) * AST + k0s + aK) * 2);
                ldsm4(ah[mt][0], ah[mt][1], ah[mt][2], ah[mt][3], a0);
            }
#pragma unroll
            for (int pair = 0; pair < 2; pair++) {
                uint32_t b0 = st + A_PLANE +
                              (uint32_t)(((k0s + bK) * BST + wn + pair * 16 + bN) * 2);
                uint32_t bh[4];
                ldsm4t(bh[0], bh[1], bh[2], bh[3], b0);
#pragma unroll
                for (int j = 0; j < 2; j++) {
                    const int nt = pair * 2 + j;
#pragma unroll
                    for (int mt = 0; mt < 4; mt++)
                        mma_f16(acc[mt][nt], ah[mt], bh[2 * j], bh[2 * j + 1]);
                }
            }
        }
    }

    // ---- epilogue ----
#pragma unroll
    for (int nt = 0; nt < 4; nt++) {
        int c = n0 + wn + nt * 8 + 2 * (lane & 3);
        float2 bb = *(const float2*)(bias + (size_t)e * NFULL + c);
#pragma unroll
        for (int mt = 0; mt < 4; mt++) {
            int r = wm + mt * 16 + (lane >> 2);
            int mrow0 = m0 + r, mrow1 = mrow0 + 8;
            if (GELU) {
                if (mrow0 < ne) {
                    float v0 = acc[mt][nt][0] + bb.x;
                    float v1 = acc[mt][nt][1] + bb.y;
                    v0 = v0 * normcdff(v0);
                    v1 = v1 * normcdff(v1);
                    *(__half2*)(OutH + (size_t)(base + mrow0) * NFULL + c) =
                        __floats2half2_rn(v0, v1);
                }
                if (mrow1 < ne) {
                    float v2 = acc[mt][nt][2] + bb.x;
                    float v3 = acc[mt][nt][3] + bb.y;
                    v2 = v2 * normcdff(v2);
                    v3 = v3 * normcdff(v3);
                    *(__half2*)(OutH + (size_t)(base + mrow1) * NFULL + c) =
                        __floats2half2_rn(v2, v3);
                }
            } else {
                if (mrow0 < ne) {
                    float2 o = { acc[mt][nt][0] + bb.x, acc[mt][nt][1] + bb.y };
                    *(float2*)(OutF + (size_t)(base + mrow0) * NFULL + c) = o;
                }
                if (mrow1 < ne) {
                    float2 o = { acc[mt][nt][2] + bb.x, acc[mt][nt][3] + bb.y };
                    *(float2*)(OutF + (size_t)(base + mrow1) * NFULL + c) = o;
                }
            }
        }
    }
}

__global__ void combine_k(float* __restrict__ y) {
    int gid = blockIdx.x * blockDim.x + threadIdx.x;
    if (gid >= T_TOK * (DIM / 4)) return;
    int t = gid >> 7;
    int q = (gid & 127) * 4;
    int s0 = g_slot[t * 2 + 0], s1 = g_slot[t * 2 + 1];
    float w0 = g_slotw[t * 2 + 0], w1 = g_slotw[t * 2 + 1];
    int r0 = g_offset[s0 >> 13] + (s0 & (MAXB - 1));
    int r1 = g_offset[s1 >> 13] + (s1 & (MAXB - 1));
    float4 a = *(const float4*)(g_oscr + (size_t)r0 * DIM + q);
    float4 b = *(const float4*)(g_oscr + (size_t)r1 * DIM + q);
    float4 o;
    o.x = w0 * a.x + w1 * b.x;
    o.y = w0 * a.y + w1 * b.y;
    o.z = w0 * a.z + w1 * b.z;
    o.w = w0 * a.w + w1 * b.w;
    *(float4*)(y + (size_t)t * DIM + q) = o;
}

}  // namespace

extern "C" void kernel_launch(void* const* d_in, const int* in_sizes, int n_in,
                              void* d_out, int out_size) {
    const float* x  = (const float*)d_in[0];
    const float* gw = (const float*)d_in[1];
    const float* w1 = (const float*)d_in[2];
    const float* b1 = (const float*)d_in[3];
    const float* w2 = (const float*)d_in[4];
    const float* b2 = (const float*)d_in[5];
    float* y    = (float*)d_out;
    float* loss = y + (out_size - 1);

    static bool attr_done = false;
    if (!attr_done) {
        cudaFuncSetAttribute((const void*)ffn_k<DIM, FDIM, true, true>,
                             cudaFuncAttributeMaxDynamicSharedMemorySize, SMEM_BYTES);
        cudaFuncSetAttribute((const void*)ffn_k<FDIM, DIM, false, false>,
                             cudaFuncAttributeMaxDynamicSharedMemorySize, SMEM_BYTES);
        attr_done = true;
    }

    __half *xh, *w1h, *w2h, *hid;
    float* oscr;
    cudaGetSymbolAddress((void**)&xh,   g_xh);
    cudaGetSymbolAddress((void**)&w1h,  g_w1h);
    cudaGetSymbolAddress((void**)&w2h,  g_w2h);
    cudaGetSymbolAddress((void**)&hid,  g_hid);
    cudaGetSymbolAddress((void**)&oscr, g_oscr);

    constexpr int W1N4 = NEXP * DIM * FDIM / 4;
    constexpr int W2N4 = NEXP * FDIM * DIM / 4;

    init_k<<<1, 32>>>();                                              // 1
    router_k<<<(T_TOK * 32 + 255) / 256, 256>>>(x, gw);               // 2 (+x conv)
    h_conv_k<<<(W1N4 + 255) / 256, 256>>>(w1, w1h, W1N4);             // 3

    ffn_k<DIM, FDIM, true, true>                                      // 4 <- ncu captures this
        <<<dim3(FDIM / BN, MAXB / BM, NEXP), 256, SMEM_BYTES>>>(xh, w1h, b1, hid, nullptr);

    h_conv_k<<<(W2N4 + 255) / 256, 256>>>(w2, w2h, W2N4);             // 5

    ffn_k<FDIM, DIM, false, false>                                    // 6
        <<<dim3(DIM / BN, MAXB / BM, NEXP), 256, SMEM_BYTES>>>(hid, w2h, b2, nullptr, oscr);

    finalize_k<<<1, 1>>>(loss);                                       // 7
    combine_k<<<(T_TOK * (DIM / 4) + 255) / 256, 256>>>(y);           // 8
}

// round 9
// speedup vs baseline: 1.0533x; 1.0533x over previous
#include <cuda_runtime.h>
#include <cuda_fp16.h>
#include <math.h>
#include <stdint.h>

namespace {

constexpr int T_TOK = 8192;
constexpr int DIM   = 512;
constexpr int FDIM  = 2048;
constexpr int NEXP  = 8;
constexpr int MAXB  = 8192;
constexpr int NROWS = 2 * T_TOK;

// CTA 128x128, 8 warps as 2(M) x 4(N), warp tile 64x32, BK=32 (fp16), 3-stage
constexpr int BM = 128, BN = 128, BK = 32;
constexpr int AST = 40;                          // A smem row stride (halves)
constexpr int BST = 136;                         // B smem row stride (halves)
constexpr int A_PLANE = BM * AST * 2;            // 10240 B
constexpr int B_PLANE = BK * BST * 2;            // 8704 B
constexpr int STAGE   = A_PLANE + B_PLANE;       // 18944 B
constexpr int NSTAGE  = 3;
constexpr int SMEM_BYTES = NSTAGE * STAGE;       // 56832 B

// ---- device scratch ----
__device__ int   g_count[NEXP];
__device__ float g_probsum[NEXP];
__device__ int   g_offset[NEXP];
__device__ int   g_tok[NEXP * MAXB];
__device__ int   g_slot[T_TOK * 2];
__device__ float g_slotw[T_TOK * 2];
__device__ __half g_xh[(size_t)T_TOK * DIM];           // fp16 x
__device__ __half g_w1h[(size_t)NEXP * DIM * FDIM];    // fp16 w1 [E][K=D][N=F]
__device__ __half g_w2h[(size_t)NEXP * FDIM * DIM];    // fp16 w2 [E][K=F][N=D]
__device__ __half g_hid[(size_t)NROWS * FDIM];         // fp16 hidden
__device__ float  g_oscr[(size_t)NROWS * DIM];

// ---- PTX helpers ----
__device__ __forceinline__ uint32_t smem_u32(const void* p) {
    uint32_t a;
    asm("{ .reg .u64 t; cvta.to.shared.u64 t, %1; cvt.u32.u64 %0, t; }" : "=r"(a) : "l"(p));
    return a;
}
__device__ __forceinline__ void cp_async16(uint32_t saddr, const void* g) {
    asm volatile("cp.async.cg.shared.global [%0], [%1], 16;" :: "r"(saddr), "l"(g));
}
__device__ __forceinline__ void cp_commit() { asm volatile("cp.async.commit_group;" ::: "memory"); }
__device__ __forceinline__ void cp_wait1()  { asm volatile("cp.async.wait_group 1;" ::: "memory"); }
__device__ __forceinline__ void cp_wait0()  { asm volatile("cp.async.wait_group 0;" ::: "memory"); }

__device__ __forceinline__ void ldsm4(uint32_t* r, uint32_t a) {
    asm volatile("ldmatrix.sync.aligned.m8n8.x4.shared.b16 {%0,%1,%2,%3}, [%4];"
                 : "=r"(r[0]), "=r"(r[1]), "=r"(r[2]), "=r"(r[3]) : "r"(a));
}
__device__ __forceinline__ void ldsm4t(uint32_t* r, uint32_t a) {
    asm volatile("ldmatrix.sync.aligned.m8n8.x4.trans.shared.b16 {%0,%1,%2,%3}, [%4];"
                 : "=r"(r[0]), "=r"(r[1]), "=r"(r[2]), "=r"(r[3]) : "r"(a));
}
__device__ __forceinline__ void mma_f16(float c[4], const uint32_t a[4],
                                        uint32_t b0, uint32_t b1) {
    asm volatile(
        "mma.sync.aligned.m16n8k16.row.col.f32.f16.f16.f32 "
        "{%0,%1,%2,%3}, {%4,%5,%6,%7}, {%8,%9}, {%0,%1,%2,%3};"
        : "+f"(c[0]), "+f"(c[1]), "+f"(c[2]), "+f"(c[3])
        : "r"(a[0]), "r"(a[1]), "r"(a[2]), "r"(a[3]), "r"(b0), "r"(b1));
}

// ---- small kernels ----
__global__ void init_k() {
    if (threadIdx.x < NEXP) { g_count[threadIdx.x] = 0; g_probsum[threadIdx.x] = 0.f; }
}

// router + fused x -> fp16 conversion
__global__ void router_k(const float* __restrict__ x, const float* __restrict__ gw) {
    __shared__ float s_gw[DIM * NEXP];
    for (int i = threadIdx.x; i < DIM * NEXP; i += blockDim.x) s_gw[i] = gw[i];
    __syncthreads();

    int t    = (int)((blockIdx.x * blockDim.x + threadIdx.x) >> 5);
    int lane = threadIdx.x & 31;
    if (t >= T_TOK) return;

    const float* xr = x + (size_t)t * DIM;
    __half* xo = g_xh + (size_t)t * DIM;
    float acc[NEXP];
#pragma unroll
    for (int e = 0; e < NEXP; e++) acc[e] = 0.f;
    for (int d = lane; d < DIM; d += 32) {
        float xv = xr[d];
        xo[d] = __float2half_rn(xv);
#pragma unroll
        for (int e = 0; e < NEXP; e++) acc[e] = fmaf(xv, s_gw[d * NEXP + e], acc[e]);
    }
#pragma unroll
    for (int off = 16; off; off >>= 1) {
#pragma unroll
        for (int e = 0; e < NEXP; e++)
            acc[e] += __shfl_xor_sync(0xffffffffu, acc[e], off);
    }
    if (lane != 0) return;

    float mx = acc[0];
#pragma unroll
    for (int e = 1; e < NEXP; e++) mx = fmaxf(mx, acc[e]);
    float p[NEXP]; float s = 0.f;
#pragma unroll
    for (int e = 0; e < NEXP; e++) { p[e] = expf(acc[e] - mx); s += p[e]; }
    float inv = 1.f / s;
#pragma unroll
    for (int e = 0; e < NEXP; e++) { p[e] *= inv; atomicAdd(&g_probsum[e], p[e]); }

    int i0 = 0;
#pragma unroll
    for (int e = 1; e < NEXP; e++) if (p[e] > p[i0]) i0 = e;
    int i1 = (i0 == 0) ? 1 : 0;
#pragma unroll
    for (int e = 0; e < NEXP; e++) if (e != i0 && p[e] > p[i1]) i1 = e;

    float w0 = p[i0], w1 = p[i1];
    float ws = 1.f / (w0 + w1);
    w0 *= ws; w1 *= ws;

    int p0 = atomicAdd(&g_count[i0], 1);
    g_tok[i0 * MAXB + p0] = t;
    g_slot[t * 2 + 0]  = i0 * MAXB + p0;
    g_slotw[t * 2 + 0] = w0;
    int p1 = atomicAdd(&g_count[i1], 1);
    g_tok[i1 * MAXB + p1] = t;
    g_slot[t * 2 + 1]  = i1 * MAXB + p1;
    g_slotw[t * 2 + 1] = w1;
}

// loss + offsets
__global__ void finalize_k(float* __restrict__ loss_out) {
    int off = 0;
    for (int e = 0; e < NEXP; e++) { g_offset[e] = off; off += g_count[e]; }
    float s = 0.f;
    for (int e = 0; e < NEXP; e++) {
        float m = g_probsum[e] * (1.f / (float)T_TOK);
        s += m * m;
    }
    *loss_out = (float)NEXP * s;
}

// fp32 -> fp16 elementwise
__global__ void h_conv_k(const float* __restrict__ src, __half* __restrict__ dst, int n4) {
    int i = blockIdx.x * blockDim.x + threadIdx.x;
    if (i >= n4) return;
    float4 v = ((const float4*)src)[i];
    ((__half2*)dst)[2 * i]     = __floats2half2_rn(v.x, v.y);
    ((__half2*)dst)[2 * i + 1] = __floats2half2_rn(v.z, v.w);
}

// ---- fp16 tensor-core FFN GEMM: D[128,128] = A[gather, K] @ B[K, N] ----
template <int KFULL, int NFULL, bool GELU, bool GATHER>
__global__ __launch_bounds__(256, 2) void ffn_k(
    const __half* __restrict__ A, const __half* __restrict__ B,
    const float* __restrict__ bias,
    __half* __restrict__ OutH, float* __restrict__ OutF) {
    const int e  = blockIdx.z;
    const int ne = g_count[e];
    const int m0 = blockIdx.y * BM;
    if (m0 >= ne) return;
    const int n0 = blockIdx.x * BN;
    int base = 0;
#pragma unroll
    for (int i = 0; i < NEXP - 1; i++) base += (i < e) ? g_count[i] : 0;

    extern __shared__ __align__(16) char smem[];
    const uint32_t sb = smem_u32(smem);
    const int tid  = threadIdx.x;
    const int lane = tid & 31;
    const int warp = tid >> 5;
    const int wm   = (warp & 1) * 64;
    const int wn   = (warp >> 1) * 32;

    // ---- cp.async addressing: 2 A-chunks + 2 B-chunks of 16B per thread ----
    const __half* sA[2];
    uint32_t dA[2];
#pragma unroll
    for (int l = 0; l < 2; l++) {
        int idx = tid + l * 256;          // 0..511
        int row = idx >> 2;               // 0..127
        int ch  = idx & 3;
        int r;
        if (GATHER) r = g_tok[e * MAXB + min(m0 + row, ne - 1)];
        else        r = base + min(m0 + row, ne - 1);
        sA[l] = A + (size_t)r * KFULL + ch * 8;
        dA[l] = (uint32_t)(row * (AST * 2) + ch * 16);
    }
    const __half* sB[2];
    uint32_t dB[2];
    const __half* Bp = B + (size_t)e * KFULL * NFULL;
#pragma unroll
    for (int l = 0; l < 2; l++) {
        int idx = tid + l * 256;
        int k  = idx >> 4;
        int ch = idx & 15;
        sB[l] = Bp + (size_t)k * NFULL + n0 + ch * 8;
        dB[l] = (uint32_t)(A_PLANE + k * (BST * 2) + ch * 16);
    }

    auto load_stage = [&](int s, int k0) {
        uint32_t st = sb + (uint32_t)(s * STAGE);
#pragma unroll
        for (int l = 0; l < 2; l++) cp_async16(st + dA[l], sA[l] + k0);
#pragma unroll
        for (int l = 0; l < 2; l++) cp_async16(st + dB[l], sB[l] + (size_t)k0 * NFULL);
    };

    // ---- hoisted fragment smem offsets (relative to stage base) ----
    const int lm = lane >> 3;
    const int aR = (lm & 1) * 8 + (lane & 7);
    const int aK = (lm >> 1) * 8;
    const int bK = (lm & 1) * 8 + (lane & 7);
    const int bN = (lm >> 1) * 8;
    uint32_t offA[4], offB[2];
#pragma unroll
    for (int mt = 0; mt < 4; mt++)
        offA[mt] = (uint32_t)(((wm + mt * 16 + aR) * AST + aK) * 2);
#pragma unroll
    for (int p = 0; p < 2; p++)
        offB[p] = (uint32_t)(A_PLANE + (bK * BST + wn + p * 16 + bN) * 2);

    float acc[4][4][4];
#pragma unroll
    for (int i = 0; i < 4; i++)
#pragma unroll
        for (int j = 0; j < 4; j++)
#pragma unroll
            for (int k = 0; k < 4; k++) acc[i][j][k] = 0.f;

    constexpr int KITERS = KFULL / BK;
    load_stage(0, 0);
    cp_commit();
    load_stage(1, BK);
    cp_commit();

    for (int it = 0; it < KITERS; it++) {
        if (it + 1 == KITERS) cp_wait0(); else cp_wait1();
        __syncthreads();
        uint32_t st = sb + (uint32_t)((it % NSTAGE) * STAGE);
#pragma unroll
        for (int ks = 0; ks < 2; ks++) {
            // batch ALL fragment loads, then all MMAs
            uint32_t ah[4][4], bh[2][4];
#pragma unroll
            for (int mt = 0; mt < 4; mt++)
                ldsm4(ah[mt], st + offA[mt] + ks * 32);          // +16 halves in K
#pragma unroll
            for (int p = 0; p < 2; p++)
                ldsm4t(bh[p], st + offB[p] + ks * (16 * BST * 2)); // +16 K-rows
#pragma unroll
            for (int p = 0; p < 2; p++)
#pragma unroll
                for (int j = 0; j < 2; j++) {
                    const int nt = p * 2 + j;
#pragma unroll
                    for (int mt = 0; mt < 4; mt++)
                        mma_f16(acc[mt][nt], ah[mt], bh[p][2 * j], bh[p][2 * j + 1]);
                }
        }
        if (it + 2 < KITERS) {
            load_stage((it + 2) % NSTAGE, (it + 2) * BK);
            cp_commit();
        }
    }

    // ---- epilogue ----
#pragma unroll
    for (int nt = 0; nt < 4; nt++) {
        int c = n0 + wn + nt * 8 + 2 * (lane & 3);
        float2 bb = *(const float2*)(bias + (size_t)e * NFULL + c);
#pragma unroll
        for (int mt = 0; mt < 4; mt++) {
            int r = wm + mt * 16 + (lane >> 2);
            int mrow0 = m0 + r, mrow1 = mrow0 + 8;
            if (GELU) {
                if (mrow0 < ne) {
                    float v0 = acc[mt][nt][0] + bb.x;
                    float v1 = acc[mt][nt][1] + bb.y;
                    v0 = v0 * normcdff(v0);
                    v1 = v1 * normcdff(v1);
                    *(__half2*)(OutH + (size_t)(base + mrow0) * NFULL + c) =
                        __floats2half2_rn(v0, v1);
                }
                if (mrow1 < ne) {
                    float v2 = acc[mt][nt][2] + bb.x;
                    float v3 = acc[mt][nt][3] + bb.y;
                    v2 = v2 * normcdff(v2);
                    v3 = v3 * normcdff(v3);
                    *(__half2*)(OutH + (size_t)(base + mrow1) * NFULL + c) =
                        __floats2half2_rn(v2, v3);
                }
            } else {
                if (mrow0 < ne) {
                    float2 o = { acc[mt][nt][0] + bb.x, acc[mt][nt][1] + bb.y };
                    *(float2*)(OutF + (size_t)(base + mrow0) * NFULL + c) = o;
                }
                if (mrow1 < ne) {
                    float2 o = { acc[mt][nt][2] + bb.x, acc[mt][nt][3] + bb.y };
                    *(float2*)(OutF + (size_t)(base + mrow1) * NFULL + c) = o;
                }
            }
        }
    }
}

__global__ void combine_k(float* __restrict__ y) {
    int gid = blockIdx.x * blockDim.x + threadIdx.x;
    if (gid >= T_TOK * (DIM / 4)) return;
    int t = gid >> 7;
    int q = (gid & 127) * 4;
    int s0 = g_slot[t * 2 + 0], s1 = g_slot[t * 2 + 1];
    float w0 = g_slotw[t * 2 + 0], w1 = g_slotw[t * 2 + 1];
    int r0 = g_offset[s0 >> 13] + (s0 & (MAXB - 1));
    int r1 = g_offset[s1 >> 13] + (s1 & (MAXB - 1));
    float4 a = *(const float4*)(g_oscr + (size_t)r0 * DIM + q);
    float4 b = *(const float4*)(g_oscr + (size_t)r1 * DIM + q);
    float4 o;
    o.x = w0 * a.x + w1 * b.x;
    o.y = w0 * a.y + w1 * b.y;
    o.z = w0 * a.z + w1 * b.z;
    o.w = w0 * a.w + w1 * b.w;
    *(float4*)(y + (size_t)t * DIM + q) = o;
}

}  // namespace

extern "C" void kernel_launch(void* const* d_in, const int* in_sizes, int n_in,
                              void* d_out, int out_size) {
    const float* x  = (const float*)d_in[0];
    const float* gw = (const float*)d_in[1];
    const float* w1 = (const float*)d_in[2];
    const float* b1 = (const float*)d_in[3];
    const float* w2 = (const float*)d_in[4];
    const float* b2 = (const float*)d_in[5];
    float* y    = (float*)d_out;
    float* loss = y + (out_size - 1);

    static bool attr_done = false;
    if (!attr_done) {
        cudaFuncSetAttribute((const void*)ffn_k<DIM, FDIM, true, true>,
                             cudaFuncAttributeMaxDynamicSharedMemorySize, SMEM_BYTES);
        cudaFuncSetAttribute((const void*)ffn_k<FDIM, DIM, false, false>,
                             cudaFuncAttributeMaxDynamicSharedMemorySize, SMEM_BYTES);
        attr_done = true;
    }

    __half *xh, *w1h, *w2h, *hid;
    float* oscr;
    cudaGetSymbolAddress((void**)&xh,   g_xh);
    cudaGetSymbolAddress((void**)&w1h,  g_w1h);
    cudaGetSymbolAddress((void**)&w2h,  g_w2h);
    cudaGetSymbolAddress((void**)&hid,  g_hid);
    cudaGetSymbolAddress((void**)&oscr, g_oscr);

    constexpr int W1N4 = NEXP * DIM * FDIM / 4;
    constexpr int W2N4 = NEXP * FDIM * DIM / 4;

    init_k<<<1, 32>>>();                                              // 1
    router_k<<<(T_TOK * 32 + 255) / 256, 256>>>(x, gw);               // 2 (+x conv)
    h_conv_k<<<(W1N4 + 255) / 256, 256>>>(w1, w1h, W1N4);             // 3

    ffn_k<DIM, FDIM, true, true>                                      // 4 <- ncu captures this
        <<<dim3(FDIM / BN, MAXB / BM, NEXP), 256, SMEM_BYTES>>>(xh, w1h, b1, hid, nullptr);

    h_conv_k<<<(W2N4 + 255) / 256, 256>>>(w2, w2h, W2N4);             // 5

    ffn_k<FDIM, DIM, false, false>                                    // 6
        <<<dim3(DIM / BN, MAXB / BM, NEXP), 256, SMEM_BYTES>>>(hid, w2h, b2, nullptr, oscr);

    finalize_k<<<1, 1>>>(loss);                                       // 7
    combine_k<<<(T_TOK * (DIM / 4) + 255) / 256, 256>>>(y);           // 8
}

// round 10
// speedup vs baseline: 1.0732x; 1.0189x over previous
#include <cuda_runtime.h>
#include <cuda_fp16.h>
#include <math.h>
#include <stdint.h>

namespace {

constexpr int T_TOK = 8192;
constexpr int DIM   = 512;
constexpr int FDIM  = 2048;
constexpr int NEXP  = 8;
constexpr int MAXB  = 8192;
constexpr int NROWS = 2 * T_TOK;

// CTA 128x128, 8 warps as 2(M) x 4(N), warp tile 64x32, BK=64 (fp16), 3-stage
constexpr int BM = 128, BN = 128, BK = 64;
constexpr int AST = 72;                          // A smem row stride (halves): 64 + 8 pad
constexpr int BST = 136;                         // B smem row stride (halves): 128 + 8 pad
constexpr int A_PLANE = BM * AST * 2;            // 18432 B
constexpr int B_PLANE = BK * BST * 2;            // 17408 B
constexpr int STAGE   = A_PLANE + B_PLANE;       // 35840 B
constexpr int NSTAGE  = 3;
constexpr int SMEM_BYTES = NSTAGE * STAGE;       // 107520 B

// ---- device scratch ----
__device__ int   g_count[NEXP];
__device__ float g_probsum[NEXP];
__device__ int   g_offset[NEXP];
__device__ int   g_tok[NEXP * MAXB];
__device__ int   g_slot[T_TOK * 2];
__device__ float g_slotw[T_TOK * 2];
__device__ __half g_xh[(size_t)T_TOK * DIM];           // fp16 x
__device__ __half g_w1h[(size_t)NEXP * DIM * FDIM];    // fp16 w1 [E][K=D][N=F]
__device__ __half g_w2h[(size_t)NEXP * FDIM * DIM];    // fp16 w2 [E][K=F][N=D]
__device__ __half g_hid[(size_t)NROWS * FDIM];         // fp16 hidden
__device__ float  g_oscr[(size_t)NROWS * DIM];

// ---- PTX helpers ----
__device__ __forceinline__ uint32_t smem_u32(const void* p) {
    uint32_t a;
    asm("{ .reg .u64 t; cvta.to.shared.u64 t, %1; cvt.u32.u64 %0, t; }" : "=r"(a) : "l"(p));
    return a;
}
__device__ __forceinline__ void cp_async16(uint32_t saddr, const void* g) {
    asm volatile("cp.async.cg.shared.global [%0], [%1], 16;" :: "r"(saddr), "l"(g));
}
__device__ __forceinline__ void cp_commit() { asm volatile("cp.async.commit_group;" ::: "memory"); }
__device__ __forceinline__ void cp_wait1()  { asm volatile("cp.async.wait_group 1;" ::: "memory"); }
__device__ __forceinline__ void cp_wait0()  { asm volatile("cp.async.wait_group 0;" ::: "memory"); }

__device__ __forceinline__ void ldsm4(uint32_t* r, uint32_t a) {
    asm volatile("ldmatrix.sync.aligned.m8n8.x4.shared.b16 {%0,%1,%2,%3}, [%4];"
                 : "=r"(r[0]), "=r"(r[1]), "=r"(r[2]), "=r"(r[3]) : "r"(a));
}
__device__ __forceinline__ void ldsm4t(uint32_t* r, uint32_t a) {
    asm volatile("ldmatrix.sync.aligned.m8n8.x4.trans.shared.b16 {%0,%1,%2,%3}, [%4];"
                 : "=r"(r[0]), "=r"(r[1]), "=r"(r[2]), "=r"(r[3]) : "r"(a));
}
__device__ __forceinline__ void mma_f16(float c[4], const uint32_t a[4],
                                        uint32_t b0, uint32_t b1) {
    asm volatile(
        "mma.sync.aligned.m16n8k16.row.col.f32.f16.f16.f32 "
        "{%0,%1,%2,%3}, {%4,%5,%6,%7}, {%8,%9}, {%0,%1,%2,%3};"
        : "+f"(c[0]), "+f"(c[1]), "+f"(c[2]), "+f"(c[3])
        : "r"(a[0]), "r"(a[1]), "r"(a[2]), "r"(a[3]), "r"(b0), "r"(b1));
}

// ---- small kernels ----
__global__ void init_k() {
    if (threadIdx.x < NEXP) { g_count[threadIdx.x] = 0; g_probsum[threadIdx.x] = 0.f; }
}

// router + fused x -> fp16 conversion
__global__ void router_k(const float* __restrict__ x, const float* __restrict__ gw) {
    __shared__ float s_gw[DIM * NEXP];
    for (int i = threadIdx.x; i < DIM * NEXP; i += blockDim.x) s_gw[i] = gw[i];
    __syncthreads();

    int t    = (int)((blockIdx.x * blockDim.x + threadIdx.x) >> 5);
    int lane = threadIdx.x & 31;
    if (t >= T_TOK) return;

    const float* xr = x + (size_t)t * DIM;
    __half* xo = g_xh + (size_t)t * DIM;
    float acc[NEXP];
#pragma unroll
    for (int e = 0; e < NEXP; e++) acc[e] = 0.f;
    for (int d = lane; d < DIM; d += 32) {
        float xv = xr[d];
        xo[d] = __float2half_rn(xv);
#pragma unroll
        for (int e = 0; e < NEXP; e++) acc[e] = fmaf(xv, s_gw[d * NEXP + e], acc[e]);
    }
#pragma unroll
    for (int off = 16; off; off >>= 1) {
#pragma unroll
        for (int e = 0; e < NEXP; e++)
            acc[e] += __shfl_xor_sync(0xffffffffu, acc[e], off);
    }
    if (lane != 0) return;

    float mx = acc[0];
#pragma unroll
    for (int e = 1; e < NEXP; e++) mx = fmaxf(mx, acc[e]);
    float p[NEXP]; float s = 0.f;
#pragma unroll
    for (int e = 0; e < NEXP; e++) { p[e] = expf(acc[e] - mx); s += p[e]; }
    float inv = 1.f / s;
#pragma unroll
    for (int e = 0; e < NEXP; e++) { p[e] *= inv; atomicAdd(&g_probsum[e], p[e]); }

    int i0 = 0;
#pragma unroll
    for (int e = 1; e < NEXP; e++) if (p[e] > p[i0]) i0 = e;
    int i1 = (i0 == 0) ? 1 : 0;
#pragma unroll
    for (int e = 0; e < NEXP; e++) if (e != i0 && p[e] > p[i1]) i1 = e;

    float w0 = p[i0], w1 = p[i1];
    float ws = 1.f / (w0 + w1);
    w0 *= ws; w1 *= ws;

    int p0 = atomicAdd(&g_count[i0], 1);
    g_tok[i0 * MAXB + p0] = t;
    g_slot[t * 2 + 0]  = i0 * MAXB + p0;
    g_slotw[t * 2 + 0] = w0;
    int p1 = atomicAdd(&g_count[i1], 1);
    g_tok[i1 * MAXB + p1] = t;
    g_slot[t * 2 + 1]  = i1 * MAXB + p1;
    g_slotw[t * 2 + 1] = w1;
}

// loss + offsets
__global__ void finalize_k(float* __restrict__ loss_out) {
    int off = 0;
    for (int e = 0; e < NEXP; e++) { g_offset[e] = off; off += g_count[e]; }
    float s = 0.f;
    for (int e = 0; e < NEXP; e++) {
        float m = g_probsum[e] * (1.f / (float)T_TOK);
        s += m * m;
    }
    *loss_out = (float)NEXP * s;
}

// fp32 -> fp16 elementwise
__global__ void h_conv_k(const float* __restrict__ src, __half* __restrict__ dst, int n4) {
    int i = blockIdx.x * blockDim.x + threadIdx.x;
    if (i >= n4) return;
    float4 v = ((const float4*)src)[i];
    ((__half2*)dst)[2 * i]     = __floats2half2_rn(v.x, v.y);
    ((__half2*)dst)[2 * i + 1] = __floats2half2_rn(v.z, v.w);
}

// ---- fp16 tensor-core FFN GEMM: D[128,128] = A[gather, K] @ B[K, N] ----
template <int KFULL, int NFULL, bool GELU, bool GATHER>
__global__ __launch_bounds__(256, 2) void ffn_k(
    const __half* __restrict__ A, const __half* __restrict__ B,
    const float* __restrict__ bias,
    __half* __restrict__ OutH, float* __restrict__ OutF) {
    const int e  = blockIdx.z;
    const int ne = g_count[e];
    const int m0 = blockIdx.y * BM;
    if (m0 >= ne) return;
    const int n0 = blockIdx.x * BN;
    int base = 0;
#pragma unroll
    for (int i = 0; i < NEXP - 1; i++) base += (i < e) ? g_count[i] : 0;

    extern __shared__ __align__(16) char smem[];
    const uint32_t sb = smem_u32(smem);
    const int tid  = threadIdx.x;
    const int lane = tid & 31;
    const int warp = tid >> 5;
    const int wm   = (warp & 1) * 64;
    const int wn   = (warp >> 1) * 32;

    // ---- cp.async addressing: 4 A-chunks + 4 B-chunks of 16B per thread ----
    // A: 128 rows x 64 halves = 1024 chunks; chunk q = tid + l*256: row=q>>3, ch=q&7
    const int arow0 = tid >> 3;          // +l*32 per slot
    const int ach   = tid & 7;
    const __half* sA[4];
#pragma unroll
    for (int l = 0; l < 4; l++) {
        int row = arow0 + l * 32;
        int r;
        if (GATHER) r = g_tok[e * MAXB + min(m0 + row, ne - 1)];
        else        r = base + min(m0 + row, ne - 1);
        sA[l] = A + (size_t)r * KFULL + ach * 8;
    }
    const uint32_t dA0 = (uint32_t)(arow0 * (AST * 2) + ach * 16);   // +l*32*AST*2
    // B: 64 rows x 128 halves = 1024 chunks; k=q>>4, ch=q&15
    const int bk0 = tid >> 4;            // +l*16 per slot
    const int bch = tid & 15;
    const __half* sB0 = B + (size_t)e * KFULL * NFULL + (size_t)bk0 * NFULL + n0 + bch * 8;
    const uint32_t dB0 = (uint32_t)(A_PLANE + bk0 * (BST * 2) + bch * 16);  // +l*16*BST*2

    auto load_stage = [&](uint32_t st, int k0) {
#pragma unroll
        for (int l = 0; l < 4; l++)
            cp_async16(st + dA0 + l * (32 * AST * 2), sA[l] + k0);
        const __half* bsrc = sB0 + (size_t)k0 * NFULL;
#pragma unroll
        for (int l = 0; l < 4; l++)
            cp_async16(st + dB0 + l * (16 * BST * 2), bsrc + (size_t)l * 16 * NFULL);
    };

    // ---- hoisted fragment smem offsets (relative to stage base) ----
    const int lm = lane >> 3;
    const int aR = (lm & 1) * 8 + (lane & 7);
    const int aK = (lm >> 1) * 8;
    const int bK = (lm & 1) * 8 + (lane & 7);
    const int bN = (lm >> 1) * 8;
    uint32_t offA[4], offB[2];
#pragma unroll
    for (int mt = 0; mt < 4; mt++)
        offA[mt] = (uint32_t)(((wm + mt * 16 + aR) * AST + aK) * 2);
#pragma unroll
    for (int p = 0; p < 2; p++)
        offB[p] = (uint32_t)(A_PLANE + (bK * BST + wn + p * 16 + bN) * 2);

    float acc[4][4][4];
#pragma unroll
    for (int i = 0; i < 4; i++)
#pragma unroll
        for (int j = 0; j < 4; j++)
#pragma unroll
            for (int k = 0; k < 4; k++) acc[i][j][k] = 0.f;

    constexpr int KITERS = KFULL / BK;
    load_stage(sb, 0);
    cp_commit();
    load_stage(sb + STAGE, BK);
    cp_commit();

    uint32_t st_c = sb;                  // compute stage (increment-wrap, no modulo)
    uint32_t st_l = sb + 2u * STAGE;     // next load stage

    for (int it = 0; it < KITERS; it++) {
        if (it + 1 == KITERS) cp_wait0(); else cp_wait1();
        __syncthreads();
#pragma unroll
        for (int ks = 0; ks < 4; ks++) {
            uint32_t ah[4][4], bh[2][4];
#pragma unroll
            for (int mt = 0; mt < 4; mt++)
                ldsm4(ah[mt], st_c + offA[mt] + ks * 32);             // +16 halves in K
#pragma unroll
            for (int p = 0; p < 2; p++)
                ldsm4t(bh[p], st_c + offB[p] + ks * (16 * BST * 2));  // +16 K-rows
#pragma unroll
            for (int p = 0; p < 2; p++)
#pragma unroll
                for (int j = 0; j < 2; j++) {
                    const int nt = p * 2 + j;
#pragma unroll
                    for (int mt = 0; mt < 4; mt++)
                        mma_f16(acc[mt][nt], ah[mt], bh[p][2 * j], bh[p][2 * j + 1]);
                }
        }
        if (it + 2 < KITERS) {
            load_stage(st_l, (it + 2) * BK);
            cp_commit();
            st_l += STAGE; if (st_l == sb + NSTAGE * STAGE) st_l = sb;
        }
        st_c += STAGE; if (st_c == sb + NSTAGE * STAGE) st_c = sb;
    }

    // ---- epilogue ----
#pragma unroll
    for (int nt = 0; nt < 4; nt++) {
        int c = n0 + wn + nt * 8 + 2 * (lane & 3);
        float2 bb = *(const float2*)(bias + (size_t)e * NFULL + c);
#pragma unroll
        for (int mt = 0; mt < 4; mt++) {
            int r = wm + mt * 16 + (lane >> 2);
            int mrow0 = m0 + r, mrow1 = mrow0 + 8;
            if (GELU) {
                if (mrow0 < ne) {
                    float v0 = acc[mt][nt][0] + bb.x;
                    float v1 = acc[mt][nt][1] + bb.y;
                    v0 = v0 * normcdff(v0);
                    v1 = v1 * normcdff(v1);
                    *(__half2*)(OutH + (size_t)(base + mrow0) * NFULL + c) =
                        __floats2half2_rn(v0, v1);
                }
                if (mrow1 < ne) {
                    float v2 = acc[mt][nt][2] + bb.x;
                    float v3 = acc[mt][nt][3] + bb.y;
                    v2 = v2 * normcdff(v2);
                    v3 = v3 * normcdff(v3);
                    *(__half2*)(OutH + (size_t)(base + mrow1) * NFULL + c) =
                        __floats2half2_rn(v2, v3);
                }
            } else {
                if (mrow0 < ne) {
                    float2 o = { acc[mt][nt][0] + bb.x, acc[mt][nt][1] + bb.y };
                    *(float2*)(OutF + (size_t)(base + mrow0) * NFULL + c) = o;
                }
                if (mrow1 < ne) {
                    float2 o = { acc[mt][nt][2] + bb.x, acc[mt][nt][3] + bb.y };
                    *(float2*)(OutF + (size_t)(base + mrow1) * NFULL + c) = o;
                }
            }
        }
    }
}

__global__ void combine_k(float* __restrict__ y) {
    int gid = blockIdx.x * blockDim.x + threadIdx.x;
    if (gid >= T_TOK * (DIM / 4)) return;
    int t = gid >> 7;
    int q = (gid & 127) * 4;
    int s0 = g_slot[t * 2 + 0], s1 = g_slot[t * 2 + 1];
    float w0 = g_slotw[t * 2 + 0], w1 = g_slotw[t * 2 + 1];
    int r0 = g_offset[s0 >> 13] + (s0 & (MAXB - 1));
    int r1 = g_offset[s1 >> 13] + (s1 & (MAXB - 1));
    float4 a = *(const float4*)(g_oscr + (size_t)r0 * DIM + q);
    float4 b = *(const float4*)(g_oscr + (size_t)r1 * DIM + q);
    float4 o;
    o.x = w0 * a.x + w1 * b.x;
    o.y = w0 * a.y + w1 * b.y;
    o.z = w0 * a.z + w1 * b.z;
    o.w = w0 * a.w + w1 * b.w;
    *(float4*)(y + (size_t)t * DIM + q) = o;
}

}  // namespace

extern "C" void kernel_launch(void* const* d_in, const int* in_sizes, int n_in,
                              void* d_out, int out_size) {
    const float* x  = (const float*)d_in[0];
    const float* gw = (const float*)d_in[1];
    const float* w1 = (const float*)d_in[2];
    const float* b1 = (const float*)d_in[3];
    const float* w2 = (const float*)d_in[4];
    const float* b2 = (const float*)d_in[5];
    float* y    = (float*)d_out;
    float* loss = y + (out_size - 1);

    static bool attr_done = false;
    if (!attr_done) {
        cudaFuncSetAttribute((const void*)ffn_k<DIM, FDIM, true, true>,
                             cudaFuncAttributeMaxDynamicSharedMemorySize, SMEM_BYTES);
        cudaFuncSetAttribute((const void*)ffn_k<FDIM, DIM, false, false>,
                             cudaFuncAttributeMaxDynamicSharedMemorySize, SMEM_BYTES);
        attr_done = true;
    }

    __half *xh, *w1h, *w2h, *hid;
    float* oscr;
    cudaGetSymbolAddress((void**)&xh,   g_xh);
    cudaGetSymbolAddress((void**)&w1h,  g_w1h);
    cudaGetSymbolAddress((void**)&w2h,  g_w2h);
    cudaGetSymbolAddress((void**)&hid,  g_hid);
    cudaGetSymbolAddress((void**)&oscr, g_oscr);

    constexpr int W1N4 = NEXP * DIM * FDIM / 4;
    constexpr int W2N4 = NEXP * FDIM * DIM / 4;

    init_k<<<1, 32>>>();                                              // 1
    router_k<<<(T_TOK * 32 + 255) / 256, 256>>>(x, gw);               // 2 (+x conv)
    h_conv_k<<<(W1N4 + 255) / 256, 256>>>(w1, w1h, W1N4);             // 3

    ffn_k<DIM, FDIM, true, true>                                      // 4 <- ncu captures this
        <<<dim3(FDIM / BN, MAXB / BM, NEXP), 256, SMEM_BYTES>>>(xh, w1h, b1, hid, nullptr);

    h_conv_k<<<(W2N4 + 255) / 256, 256>>>(w2, w2h, W2N4);             // 5

    ffn_k<FDIM, DIM, false, false>                                    // 6
        <<<dim3(DIM / BN, MAXB / BM, NEXP), 256, SMEM_BYTES>>>(hid, w2h, b2, nullptr, oscr);

    finalize_k<<<1, 1>>>(loss);                                       // 7
    combine_k<<<(T_TOK * (DIM / 4) + 255) / 256, 256>>>(y);           // 8
}

// round 12
// speedup vs baseline: 1.1046x; 1.0292x over previous
#include <cuda_runtime.h>
#include <cuda_fp16.h>
#include <math.h>
#include <stdint.h>

namespace {

constexpr int T_TOK = 8192;
constexpr int DIM   = 512;
constexpr int FDIM  = 2048;
constexpr int NEXP  = 8;
constexpr int MAXB  = 8192;
constexpr int NROWS = 2 * T_TOK;

// CTA 128x128, 8 warps as 2(M) x 4(N), warp tile 64x32, BK=64 (fp16), 3-stage
constexpr int BM = 128, BN = 128, BK = 64;
constexpr int AST = 72;                          // A smem row stride (halves): 64 + 8 pad
constexpr int BST = 136;                         // B smem row stride (halves): 128 + 8 pad
constexpr int A_PLANE = BM * AST * 2;            // 18432 B
constexpr int B_PLANE = BK * BST * 2;            // 17408 B
constexpr int STAGE   = A_PLANE + B_PLANE;       // 35840 B
constexpr int NSTAGE  = 3;
constexpr int SMEM_BYTES = NSTAGE * STAGE;       // 107520 B

// ---- device scratch ----
__device__ int   g_count[NEXP];
__device__ float g_probsum[NEXP];
__device__ int   g_offset[NEXP];
__device__ int   g_tok[NEXP * MAXB];
__device__ int   g_slot[T_TOK * 2];
__device__ float g_slotw[T_TOK * 2];
__device__ __half g_xh[(size_t)T_TOK * DIM];           // fp16 x
__device__ __half g_w1h[(size_t)NEXP * DIM * FDIM];    // fp16 w1 [E][K=D][N=F]
__device__ __half g_w2h[(size_t)NEXP * FDIM * DIM];    // fp16 w2 [E][K=F][N=D]
__device__ __half g_hid[(size_t)NROWS * FDIM];         // fp16 hidden
__device__ float  g_oscr[(size_t)NROWS * DIM];

// ---- PTX helpers ----
__device__ __forceinline__ uint32_t smem_u32(const void* p) {
    uint32_t a;
    asm("{ .reg .u64 t; cvta.to.shared.u64 t, %1; cvt.u32.u64 %0, t; }" : "=r"(a) : "l"(p));
    return a;
}
__device__ __forceinline__ void cp_async16(uint32_t saddr, const void* g) {
    asm volatile("cp.async.cg.shared.global [%0], [%1], 16;" :: "r"(saddr), "l"(g));
}
__device__ __forceinline__ void cp_commit() { asm volatile("cp.async.commit_group;" ::: "memory"); }
__device__ __forceinline__ void cp_wait1()  { asm volatile("cp.async.wait_group 1;" ::: "memory"); }
__device__ __forceinline__ void cp_wait0()  { asm volatile("cp.async.wait_group 0;" ::: "memory"); }

__device__ __forceinline__ void ldsm4(uint32_t* r, uint32_t a) {
    asm volatile("ldmatrix.sync.aligned.m8n8.x4.shared.b16 {%0,%1,%2,%3}, [%4];"
                 : "=r"(r[0]), "=r"(r[1]), "=r"(r[2]), "=r"(r[3]) : "r"(a));
}
__device__ __forceinline__ void ldsm4t(uint32_t* r, uint32_t a) {
    asm volatile("ldmatrix.sync.aligned.m8n8.x4.trans.shared.b16 {%0,%1,%2,%3}, [%4];"
                 : "=r"(r[0]), "=r"(r[1]), "=r"(r[2]), "=r"(r[3]) : "r"(a));
}
__device__ __forceinline__ void mma_f16(float c[4], const uint32_t a[4],
                                        uint32_t b0, uint32_t b1) {
    asm volatile(
        "mma.sync.aligned.m16n8k16.row.col.f32.f16.f16.f32 "
        "{%0,%1,%2,%3}, {%4,%5,%6,%7}, {%8,%9}, {%0,%1,%2,%3};"
        : "+f"(c[0]), "+f"(c[1]), "+f"(c[2]), "+f"(c[3])
        : "r"(a[0]), "r"(a[1]), "r"(a[2]), "r"(a[3]), "r"(b0), "r"(b1));
}

// ---- small kernels ----
__global__ void init_k() {
    if (threadIdx.x < NEXP) { g_count[threadIdx.x] = 0; g_probsum[threadIdx.x] = 0.f; }
}

// router + fused x -> fp16 conversion
__global__ void router_k(const float* __restrict__ x, const float* __restrict__ gw) {
    __shared__ float s_gw[DIM * NEXP];
    for (int i = threadIdx.x; i < DIM * NEXP; i += blockDim.x) s_gw[i] = gw[i];
    __syncthreads();

    int t    = (int)((blockIdx.x * blockDim.x + threadIdx.x) >> 5);
    int lane = threadIdx.x & 31;
    if (t >= T_TOK) return;

    const float* xr = x + (size_t)t * DIM;
    __half* xo = g_xh + (size_t)t * DIM;
    float acc[NEXP];
#pragma unroll
    for (int e = 0; e < NEXP; e++) acc[e] = 0.f;
    for (int d = lane; d < DIM; d += 32) {
        float xv = xr[d];
        xo[d] = __float2half_rn(xv);
#pragma unroll
        for (int e = 0; e < NEXP; e++) acc[e] = fmaf(xv, s_gw[d * NEXP + e], acc[e]);
    }
#pragma unroll
    for (int off = 16; off; off >>= 1) {
#pragma unroll
        for (int e = 0; e < NEXP; e++)
            acc[e] += __shfl_xor_sync(0xffffffffu, acc[e], off);
    }
    if (lane != 0) return;

    float mx = acc[0];
#pragma unroll
    for (int e = 1; e < NEXP; e++) mx = fmaxf(mx, acc[e]);
    float p[NEXP]; float s = 0.f;
#pragma unroll
    for (int e = 0; e < NEXP; e++) { p[e] = expf(acc[e] - mx); s += p[e]; }
    float inv = 1.f / s;
#pragma unroll
    for (int e = 0; e < NEXP; e++) { p[e] *= inv; atomicAdd(&g_probsum[e], p[e]); }

    int i0 = 0;
#pragma unroll
    for (int e = 1; e < NEXP; e++) if (p[e] > p[i0]) i0 = e;
    int i1 = (i0 == 0) ? 1 : 0;
#pragma unroll
    for (int e = 0; e < NEXP; e++) if (e != i0 && p[e] > p[i1]) i1 = e;

    float w0 = p[i0], w1 = p[i1];
    float ws = 1.f / (w0 + w1);
    w0 *= ws; w1 *= ws;

    int p0 = atomicAdd(&g_count[i0], 1);
    g_tok[i0 * MAXB + p0] = t;
    g_slot[t * 2 + 0]  = i0 * MAXB + p0;
    g_slotw[t * 2 + 0] = w0;
    int p1 = atomicAdd(&g_count[i1], 1);
    g_tok[i1 * MAXB + p1] = t;
    g_slot[t * 2 + 1]  = i1 * MAXB + p1;
    g_slotw[t * 2 + 1] = w1;
}

// loss + offsets
__global__ void finalize_k(float* __restrict__ loss_out) {
    int off = 0;
    for (int e = 0; e < NEXP; e++) { g_offset[e] = off; off += g_count[e]; }
    float s = 0.f;
    for (int e = 0; e < NEXP; e++) {
        float m = g_probsum[e] * (1.f / (float)T_TOK);
        s += m * m;
    }
    *loss_out = (float)NEXP * s;
}

// fp32 -> fp16 elementwise
__global__ void h_conv_k(const float* __restrict__ src, __half* __restrict__ dst, int n4) {
    int i = blockIdx.x * blockDim.x + threadIdx.x;
    if (i >= n4) return;
    float4 v = ((const float4*)src)[i];
    ((__half2*)dst)[2 * i]     = __floats2half2_rn(v.x, v.y);
    ((__half2*)dst)[2 * i + 1] = __floats2half2_rn(v.z, v.w);
}

// ---- fp16 tensor-core FFN GEMM: D[128,128] = A[gather, K] @ B[K, N] ----
template <int KFULL, int NFULL, bool GELU, bool GATHER>
__global__ __launch_bounds__(256, 2) void ffn_k(
    const __half* __restrict__ A, const __half* __restrict__ B,
    const float* __restrict__ bias,
    __half* __restrict__ OutH, float* __restrict__ OutF) {
    const int e  = blockIdx.z;
    const int ne = g_count[e];
    const int m0 = blockIdx.y * BM;
    if (m0 >= ne) return;
    const int n0 = blockIdx.x * BN;
    int base = 0;
#pragma unroll
    for (int i = 0; i < NEXP - 1; i++) base += (i < e) ? g_count[i] : 0;

    extern __shared__ __align__(16) char smem[];
    const uint32_t sb = smem_u32(smem);
    const int tid  = threadIdx.x;
    const int lane = tid & 31;
    const int warp = tid >> 5;
    const int wm   = (warp & 1) * 64;
    const int wn   = (warp >> 1) * 32;

    // ---- cp.async addressing: 4 A-chunks + 4 B-chunks of 16B per thread ----
    const int arow0 = tid >> 3;          // +l*32 per slot
    const int ach   = tid & 7;
    const __half* sA[4];
#pragma unroll
    for (int l = 0; l < 4; l++) {
        int row = arow0 + l * 32;
        int r;
        if (GATHER) r = g_tok[e * MAXB + min(m0 + row, ne - 1)];
        else        r = base + min(m0 + row, ne - 1);
        sA[l] = A + (size_t)r * KFULL + ach * 8;
    }
    const uint32_t dA0 = (uint32_t)(arow0 * (AST * 2) + ach * 16);
    const int bk0 = tid >> 4;            // +l*16 per slot
    const int bch = tid & 15;
    const __half* sB0 = B + (size_t)e * KFULL * NFULL + (size_t)bk0 * NFULL + n0 + bch * 8;
    const uint32_t dB0 = (uint32_t)(A_PLANE + bk0 * (BST * 2) + bch * 16);

    auto load_stage = [&](uint32_t st, int k0) {
#pragma unroll
        for (int l = 0; l < 4; l++)
            cp_async16(st + dA0 + l * (32 * AST * 2), sA[l] + k0);
        const __half* bsrc = sB0 + (size_t)k0 * NFULL;
#pragma unroll
        for (int l = 0; l < 4; l++)
            cp_async16(st + dB0 + l * (16 * BST * 2), bsrc + (size_t)l * 16 * NFULL);
    };

    // ---- hoisted fragment smem offsets ----
    const int lm = lane >> 3;
    const int aR = (lm & 1) * 8 + (lane & 7);
    const int aK = (lm >> 1) * 8;
    const int bK = (lm & 1) * 8 + (lane & 7);
    const int bN = (lm >> 1) * 8;
    uint32_t offA[4], offB[2];
#pragma unroll
    for (int mt = 0; mt < 4; mt++)
        offA[mt] = (uint32_t)(((wm + mt * 16 + aR) * AST + aK) * 2);
#pragma unroll
    for (int p = 0; p < 2; p++)
        offB[p] = (uint32_t)(A_PLANE + (bK * BST + wn + p * 16 + bN) * 2);

    float acc[4][4][4];
#pragma unroll
    for (int i = 0; i < 4; i++)
#pragma unroll
        for (int j = 0; j < 4; j++)
#pragma unroll
            for (int k = 0; k < 4; k++) acc[i][j][k] = 0.f;

    constexpr int KITERS = KFULL / BK;
    load_stage(sb, 0);
    cp_commit();
    load_stage(sb + STAGE, BK);
    cp_commit();

    uint32_t st_c = sb;
    uint32_t st_l = sb + 2u * STAGE;

    for (int it = 0; it < KITERS; it++) {
        if (it + 1 == KITERS) cp_wait0(); else cp_wait1();
        __syncthreads();
#pragma unroll
        for (int ks = 0; ks < 4; ks++) {
            uint32_t ah[4][4], bh[2][4];
#pragma unroll
            for (int mt = 0; mt < 4; mt++)
                ldsm4(ah[mt], st_c + offA[mt] + ks * 32);
#pragma unroll
            for (int p = 0; p < 2; p++)
                ldsm4t(bh[p], st_c + offB[p] + ks * (16 * BST * 2));
#pragma unroll
            for (int p = 0; p < 2; p++)
#pragma unroll
                for (int j = 0; j < 2; j++) {
                    const int nt = p * 2 + j;
#pragma unroll
                    for (int mt = 0; mt < 4; mt++)
                        mma_f16(acc[mt][nt], ah[mt], bh[p][2 * j], bh[p][2 * j + 1]);
                }
        }
        if (it + 2 < KITERS) {
            load_stage(st_l, (it + 2) * BK);
            cp_commit();
            st_l += STAGE; if (st_l == sb + NSTAGE * STAGE) st_l = sb;
        }
        st_c += STAGE; if (st_c == sb + NSTAGE * STAGE) st_c = sb;
    }

    // ---- epilogue ----
#pragma unroll
    for (int nt = 0; nt < 4; nt++) {
        int c = n0 + wn + nt * 8 + 2 * (lane & 3);
        float2 bb = *(const float2*)(bias + (size_t)e * NFULL + c);
#pragma unroll
        for (int mt = 0; mt < 4; mt++) {
            int r = wm + mt * 16 + (lane >> 2);
            int mrow0 = m0 + r, mrow1 = mrow0 + 8;
            if (GELU) {
                if (mrow0 < ne) {
                    float v0 = acc[mt][nt][0] + bb.x;
                    float v1 = acc[mt][nt][1] + bb.y;
                    v0 = v0 * normcdff(v0);
                    v1 = v1 * normcdff(v1);
                    *(__half2*)(OutH + (size_t)(base + mrow0) * NFULL + c) =
                        __floats2half2_rn(v0, v1);
                }
                if (mrow1 < ne) {
                    float v2 = acc[mt][nt][2] + bb.x;
                    float v3 = acc[mt][nt][3] + bb.y;
                    v2 = v2 * normcdff(v2);
                    v3 = v3 * normcdff(v3);
                    *(__half2*)(OutH + (size_t)(base + mrow1) * NFULL + c) =
                        __floats2half2_rn(v2, v3);
                }
            } else {
                if (mrow0 < ne) {
                    float2 o = { acc[mt][nt][0] + bb.x, acc[mt][nt][1] + bb.y };
                    *(float2*)(OutF + (size_t)(base + mrow0) * NFULL + c) = o;
                }
                if (mrow1 < ne) {
                    float2 o = { acc[mt][nt][2] + bb.x, acc[mt][nt][3] + bb.y };
                    *(float2*)(OutF + (size_t)(base + mrow1) * NFULL + c) = o;
                }
            }
        }
    }
}

__global__ void combine_k(float* __restrict__ y) {
    int gid = blockIdx.x * blockDim.x + threadIdx.x;
    if (gid >= T_TOK * (DIM / 4)) return;
    int t = gid >> 7;
    int q = (gid & 127) * 4;
    int s0 = g_slot[t * 2 + 0], s1 = g_slot[t * 2 + 1];
    float w0 = g_slotw[t * 2 + 0], w1 = g_slotw[t * 2 + 1];
    int r0 = g_offset[s0 >> 13] + (s0 & (MAXB - 1));
    int r1 = g_offset[s1 >> 13] + (s1 & (MAXB - 1));
    float4 a = *(const float4*)(g_oscr + (size_t)r0 * DIM + q);
    float4 b = *(const float4*)(g_oscr + (size_t)r1 * DIM + q);
    float4 o;
    o.x = w0 * a.x + w1 * b.x;
    o.y = w0 * a.y + w1 * b.y;
    o.z = w0 * a.z + w1 * b.z;
    o.w = w0 * a.w + w1 * b.w;
    *(float4*)(y + (size_t)t * DIM + q) = o;
}

}  // namespace

extern "C" void kernel_launch(void* const* d_in, const int* in_sizes, int n_in,
                              void* d_out, int out_size) {
    const float* x  = (const float*)d_in[0];
    const float* gw = (const float*)d_in[1];
    const float* w1 = (const float*)d_in[2];
    const float* b1 = (const float*)d_in[3];
    const float* w2 = (const float*)d_in[4];
    const float* b2 = (const float*)d_in[5];
    float* y    = (float*)d_out;
    float* loss = y + (out_size - 1);

    static cudaStream_t s1 = nullptr;
    static cudaEvent_t eFork = nullptr, e1 = nullptr, e2 = nullptr;
    static bool attr_done = false;
    if (!attr_done) {
        cudaFuncSetAttribute((const void*)ffn_k<DIM, FDIM, true, true>,
                             cudaFuncAttributeMaxDynamicSharedMemorySize, SMEM_BYTES);
        cudaFuncSetAttribute((const void*)ffn_k<FDIM, DIM, false, false>,
                             cudaFuncAttributeMaxDynamicSharedMemorySize, SMEM_BYTES);
        cudaStreamCreateWithFlags(&s1, cudaStreamNonBlocking);
        cudaEventCreateWithFlags(&eFork, cudaEventDisableTiming);
        cudaEventCreateWithFlags(&e1, cudaEventDisableTiming);
        cudaEventCreateWithFlags(&e2, cudaEventDisableTiming);
        attr_done = true;
    }

    __half *xh, *w1h, *w2h, *hid;
    float* oscr;
    cudaGetSymbolAddress((void**)&xh,   g_xh);
    cudaGetSymbolAddress((void**)&w1h,  g_w1h);
    cudaGetSymbolAddress((void**)&w2h,  g_w2h);
    cudaGetSymbolAddress((void**)&hid,  g_hid);
    cudaGetSymbolAddress((void**)&oscr, g_oscr);

    constexpr int W1N4 = NEXP * DIM * FDIM / 4;
    constexpr int W2N4 = NEXP * FDIM * DIM / 4;

    // main stream: init -> router -> ffn1 -> ffn2 -> finalize -> combine
    // side stream s1: convW1 (|| router), convW2 (|| ffn1); joined via events.
    init_k<<<1, 32>>>();                                              // launch 1
    cudaEventRecord(eFork, 0);
    cudaStreamWaitEvent(s1, eFork, 0);

    h_conv_k<<<(W1N4 + 255) / 256, 256, 0, s1>>>(w1, w1h, W1N4);      // launch 2 (s1)
    cudaEventRecord(e1, s1);

    router_k<<<(T_TOK * 32 + 255) / 256, 256>>>(x, gw);               // launch 3 (+x conv)

    cudaStreamWaitEvent(0, e1, 0);                                    // ffn1 needs w1h
    ffn_k<DIM, FDIM, true, true>                                      // launch 4 <- ncu
        <<<dim3(FDIM / BN, MAXB / BM, NEXP), 256, SMEM_BYTES>>>(xh, w1h, b1, hid, nullptr);

    h_conv_k<<<(W2N4 + 255) / 256, 256, 0, s1>>>(w2, w2h, W2N4);      // launch 5 (s1, || ffn1)
    cudaEventRecord(e2, s1);

    cudaStreamWaitEvent(0, e2, 0);                                    // ffn2 needs w2h
    ffn_k<FDIM, DIM, false, false>                                    // launch 6
        <<<dim3(DIM / BN, MAXB / BM, NEXP), 256, SMEM_BYTES>>>(hid, w2h, b2, nullptr, oscr);

    finalize_k<<<1, 1>>>(loss);                                       // launch 7
    combine_k<<<(T_TOK * (DIM / 4) + 255) / 256, 256>>>(y);           // launch 8
}